// round 6
// baseline (speedup 1.0000x reference)
#include <cuda_runtime.h>
#include <cstdint>

namespace {

constexpr int NT = 512;  // threads per CTA (16 warps)
using u64 = unsigned long long;

struct Smem {
  float F [64][64];
  float S [64][64];      // side state: H (side0) or T (side1)
  float U [64][64];      // xcat staging, then F + LN-out
  float W [64][64];      // w1 or w2
  float TR[64][64];      // transform; reused as Phase-C partial scratch
  float WE[64][64];      // cor[j] * S[j][:]
  float SAV[2][64][64];  // saved S layers 1,2 (all rows)
  unsigned m0[64], m1[64];   // adjacency bitmasks
  float degf[64];
  float gmm[64], bet[64], bias[64];
  unsigned fr0[4], fr1[4];   // frontier words per hop 0..3
  int   cnt[3];
  unsigned char tasks[3][64];
};

__device__ __forceinline__ float rsum16(float v, unsigned m) {
  v += __shfl_xor_sync(m, v, 8);
  v += __shfl_xor_sync(m, v, 4);
  v += __shfl_xor_sync(m, v, 2);
  v += __shfl_xor_sync(m, v, 1);
  return v;
}
__device__ __forceinline__ float rsum32(float v) {
  #pragma unroll
  for (int o = 16; o > 0; o >>= 1) v += __shfl_xor_sync(0xFFFFFFFFu, v, o);
  return v;
}
__device__ __forceinline__ u64 pk1(float s) {
  u64 r; asm("mov.b64 %0, {%1, %1};" : "=l"(r) : "r"(__float_as_uint(s))); return r;
}
__device__ __forceinline__ u64 pk2(float x, float y) {
  u64 r; asm("mov.b64 %0, {%1, %2};" : "=l"(r) : "r"(__float_as_uint(x)), "r"(__float_as_uint(y))); return r;
}
__device__ __forceinline__ void upk(u64 v, float& x, float& y) {
  unsigned a, b; asm("mov.b64 {%0, %1}, %2;" : "=r"(a), "=r"(b) : "l"(v));
  x = __uint_as_float(a); y = __uint_as_float(b);
}
__device__ __forceinline__ u64 fma2(u64 a, u64 b, u64 c) {
  u64 d; asm("fma.rn.f32x2 %0, %1, %2, %3;" : "=l"(d) : "l"(a), "l"(b), "l"(c)); return d;
}
__device__ __forceinline__ u64 add2(u64 a, u64 b) {
  u64 d; asm("add.rn.f32x2 %0, %1, %2;" : "=l"(d) : "l"(a), "l"(b)); return d;
}
__device__ __forceinline__ void add4(float4& a, const float4& b) {
  a.x += b.x; a.y += b.y; a.z += b.z; a.w += b.w;
}
__device__ __forceinline__ void relu4(float4& a) {
  a.x = fmaxf(a.x, 0.f); a.y = fmaxf(a.y, 0.f);
  a.z = fmaxf(a.z, 0.f); a.w = fmaxf(a.w, 0.f);
}
__device__ __forceinline__ bool bitr(unsigned w0, unsigned w1, int r) {
  return ((r < 32 ? (w0 >> r) : (w1 >> (r - 32))) & 1u) != 0u;
}
__device__ __forceinline__ uint32_t smem_u32(const void* p) {
  uint32_t a;
  asm("{ .reg .u64 t; cvta.to.shared.u64 t, %1; cvt.u32.u64 %0, t; }" : "=r"(a) : "l"(p));
  return a;
}
__device__ __forceinline__ uint32_t mapa_u32(uint32_t addr, uint32_t rank) {
  uint32_t r;
  asm("mapa.shared::cluster.u32 %0, %1, %2;" : "=r"(r) : "r"(addr), "r"(rank));
  return r;
}
__device__ __forceinline__ float4 ld_ds4(uint32_t addr) {
  uint32_t a, b, c, d;
  asm volatile("ld.shared::cluster.v4.b32 {%0,%1,%2,%3}, [%4];"
               : "=r"(a), "=r"(b), "=r"(c), "=r"(d) : "r"(addr));
  float4 v;
  v.x = __uint_as_float(a); v.y = __uint_as_float(b);
  v.z = __uint_as_float(c); v.w = __uint_as_float(d);
  return v;
}
#define CL_ARRIVE() asm volatile("barrier.cluster.arrive.aligned;" ::: "memory")
#define CL_WAIT()   asm volatile("barrier.cluster.wait.aligned;"   ::: "memory")

// packed pair accumulator for a float4 worth of output
struct Acc4 { u64 lo, hi; };
__device__ __forceinline__ void afma(Acc4& a, u64 sp, const ulonglong2& wq) {
  a.lo = fma2(sp, wq.x, a.lo);
  a.hi = fma2(sp, wq.y, a.hi);
}
__device__ __forceinline__ float4 aunpk(const Acc4& a) {
  float4 r; upk(a.lo, r.x, r.y); upk(a.hi, r.z, r.w); return r;
}

__global__ __launch_bounds__(NT, 1) __cluster_dims__(2, 1, 1)
void lagat_kernel(const float* __restrict__ adj,
                  const float* __restrict__ feat_node,
                  const int*   __restrict__ idx,
                  const int*   __restrict__ head_ids,
                  const int*   __restrict__ tail_ids,
                  const float* __restrict__ transform,
                  const float* __restrict__ embed,
                  const float* __restrict__ w1, const float* __restrict__ b1,
                  const float* __restrict__ w2, const float* __restrict__ b2,
                  const float* __restrict__ gamma1, const float* __restrict__ beta1,
                  const float* __restrict__ gamma2, const float* __restrict__ beta2,
                  float* __restrict__ out)
{
  extern __shared__ float smem_raw[];
  Smem& s = *reinterpret_cast<Smem*>(smem_raw);
  const int g    = blockIdx.x >> 1;
  const int side = blockIdx.x & 1;      // 0 = head chain, 1 = tail chain
  const int tid  = threadIdx.x;
  const int w    = tid >> 5;
  const int l    = tid & 31;
  const int li   = l & 15;
  const int h16  = l >> 4;
  const int hw   = w * 2 + h16;         // half-warp id 0..31
  const unsigned hm = (l < 16) ? 0x0000FFFFu : 0xFFFF0000u;
  const int base = g * 64;

  // ---- earliest: start the dependent idx -> embed chain and scalars --------
  const int xrow = tid >> 3, xcol = tid & 7;
  const int id = idx[base + xrow];                       // LDG #1 of chain
  const int hl = head_ids[g] - base;
  const int tl = tail_ids[g] - base;

  float4* F4  = reinterpret_cast<float4*>(&s.F [0][0]);
  float4* S4  = reinterpret_cast<float4*>(&s.S [0][0]);
  float4* U4  = reinterpret_cast<float4*>(&s.U [0][0]);
  float4* W4  = reinterpret_cast<float4*>(&s.W [0][0]);
  float4* TR4 = reinterpret_cast<float4*>(&s.TR[0][0]);
  float4* P4  = TR4;                    // Phase-C partial scratch (TR dead after P1)
  float4* WE4 = reinterpret_cast<float4*>(&s.WE[0][0]);
  float4* SV4 = reinterpret_cast<float4*>(&s.SAV[0][0][0]);
  const ulonglong2* W8  = reinterpret_cast<const ulonglong2*>(&s.W [0][0]);
  const ulonglong2* TR8 = reinterpret_cast<const ulonglong2*>(&s.TR[0][0]);
  const u64*    WEq = reinterpret_cast<const u64*>(&s.WE[0][0]);
  const float2* F2  = reinterpret_cast<const float2*>(&s.F[0][0]);
  float2*       U2  = reinterpret_cast<float2*>(&s.U[0][0]);
  const float2* gm2 = reinterpret_cast<const float2*>(s.gmm);
  const float2* bt2 = reinterpret_cast<const float2*>(s.bet);
  const float4* bi4 = reinterpret_cast<const float4*>(s.bias);

  const uint32_t sbase   = smem_u32(&s);
  const uint32_t off_F   = (uint32_t)((const char*)&s.F[0][0]      - (const char*)&s);
  const uint32_t off_S   = (uint32_t)((const char*)&s.S[0][0]      - (const char*)&s);
  const uint32_t off_SAV = (uint32_t)((const char*)&s.SAV[0][0][0] - (const char*)&s);
  const uint32_t pbase   = mapa_u32(sbase, (uint32_t)(side ^ 1));

  const int c_own = side ? tl : hl;   // BFS center for this chain
  const int c_qry = side ? hl : tl;   // query center (opposite)

  const float* Wsrc = side ? w2 : w1;
  const float* Gsrc = side ? gamma2 : gamma1;
  const float* Bsrc = side ? beta2  : beta1;
  const float* bsrc = side ? b2 : b1;

  // ---------------- P0: loads + adjacency bitmask ---------------------------
  // embed gather (LDG #2 of chain) issued before the bulk loads
  const float4 xg = *reinterpret_cast<const float4*>(embed + (size_t)id * 32 + xcol * 4);
  const float4 xf = *reinterpret_cast<const float4*>(feat_node + (base + xrow) * 32 + xcol * 4);
  {
    float av[4][2];
    #pragma unroll
    for (int rr = 0; rr < 4; ++rr) {
      const float* arow = adj + (size_t)(base + w * 4 + rr) * 4096 + base;
      av[rr][0] = arow[l];
      av[rr][1] = arow[l + 32];
    }
    #pragma unroll
    for (int rr = 0; rr < 4; ++rr) {
      const unsigned b0 = __ballot_sync(0xFFFFFFFFu, av[rr][0] != 0.f);
      const unsigned b1 = __ballot_sync(0xFFFFFFFFu, av[rr][1] != 0.f);
      if (l == 0) {
        const int r = w * 4 + rr;
        s.m0[r] = b0; s.m1[r] = b1;
        s.degf[r] = (float)(__popc(b0) + __popc(b1));
      }
    }
  }
  #pragma unroll
  for (int e = tid; e < 1024; e += NT) {
    TR4[e] = reinterpret_cast<const float4*>(transform)[e];
    W4[e]  = reinterpret_cast<const float4*>(Wsrc)[e];
  }
  U4[xrow * 16 + xcol]     = xf;
  U4[xrow * 16 + 8 + xcol] = xg;
  if (tid < 64) {
    s.gmm[tid] = Gsrc[tid]; s.bet[tid] = Bsrc[tid]; s.bias[tid] = bsrc[tid];
  }
  __syncthreads();

  // ---------------- P1: F rows of OWN half (1 row per half-warp, packed) ----
  {
    const int r = side * 32 + hw;
    Acc4 acc; acc.lo = 0ull; acc.hi = 0ull;
    #pragma unroll
    for (int kb = 0; kb < 16; ++kb) {
      const float4 xv = U4[r * 16 + kb];
      afma(acc, pk1(xv.x), TR8[(4 * kb + 0) * 16 + li]);
      afma(acc, pk1(xv.y), TR8[(4 * kb + 1) * 16 + li]);
      afma(acc, pk1(xv.z), TR8[(4 * kb + 2) * 16 + li]);
      afma(acc, pk1(xv.w), TR8[(4 * kb + 3) * 16 + li]);
    }
    const float4 a = aunpk(acc);
    F4[r * 16 + li] = a;
    S4[r * 16 + li] = a;
    *reinterpret_cast<float4*>(out + (size_t)(base + r) * 256 + li * 4) = a;
  }

  // arrive early: our F half + masks are committed; overlap frontier compute
  CL_ARRIVE();

  // ---------------- frontier masks (hops 0..3) + task lists (warp 0) --------
  if (w == 0) {
    const unsigned c0bit = (c_own < 32) ? 1u << c_own : 0u;
    const unsigned c1bit = (c_own >= 32) ? 1u << (c_own - 32) : 0u;
    const unsigned f1_0 = s.m0[c_own] | c0bit;
    const unsigned f1_1 = s.m1[c_own] | c1bit;
    const bool a2 = bitr(f1_0, f1_1, l)      || (s.m0[l] & f1_0)      || (s.m1[l] & f1_1);
    const bool b2 = bitr(f1_0, f1_1, l + 32) || (s.m0[l + 32] & f1_0) || (s.m1[l + 32] & f1_1);
    const unsigned f2_0 = __ballot_sync(0xFFFFFFFFu, a2);
    const unsigned f2_1 = __ballot_sync(0xFFFFFFFFu, b2);
    const bool a3 = bitr(f2_0, f2_1, l)      || (s.m0[l] & f2_0)      || (s.m1[l] & f2_1);
    const bool b3 = bitr(f2_0, f2_1, l + 32) || (s.m0[l + 32] & f2_0) || (s.m1[l + 32] & f2_1);
    const unsigned f3_0 = __ballot_sync(0xFFFFFFFFu, a3);
    const unsigned f3_1 = __ballot_sync(0xFFFFFFFFu, b3);
    unsigned fw0[4] = { c0bit, f1_0, f2_0, f3_0 };
    unsigned fw1[4] = { c1bit, f1_1, f2_1, f3_1 };
    const unsigned below = (1u << l) - 1u;
    #pragma unroll
    for (int hp = 0; hp < 4; ++hp) {
      if (l == 0) { s.fr0[hp] = fw0[hp]; s.fr1[hp] = fw1[hp]; }
      if (hp < 3) {
        if ((fw0[hp] >> l) & 1u) s.tasks[hp][__popc(fw0[hp] & below)] = (unsigned char)l;
        if ((fw1[hp] >> l) & 1u) s.tasks[hp][__popc(fw0[hp]) + __popc(fw1[hp] & below)] = (unsigned char)(l + 32);
        if (l == 0) s.cnt[hp] = __popc(fw0[hp]) + __popc(fw1[hp]);
      }
    }
  }

  // ---------------- exchange F halves via DSMEM -----------------------------
  CL_WAIT();
  {
    const int r = (side ^ 1) * 32 + (tid >> 4), c4 = tid & 15;
    const float4 v = ld_ds4(pbase + off_F + (uint32_t)(r * 16 + c4) * 16u);
    F4[r * 16 + c4] = v;
    S4[r * 16 + c4] = v;
  }
  __syncthreads();

  // ---------------- main loop: it = 0,1,2 (hop = 2,1,0) ---------------------
  for (int it = 0; it < 3; ++it) {
    const int hop = 2 - it;
    const int cnt = s.cnt[hop];

    // Phase A: save layer-`it` state (it>0); WE for rows in fr[hop+1]
    {
      const unsigned nb0 = s.fr0[hop + 1], nb1 = s.fr1[hop + 1];
      const float4 q = F4[c_qry * 16 + li];
      #pragma unroll
      for (int p = 0; p < 2; ++p) {
        const int r = w * 4 + p * 2 + h16;
        const float4 sv = S4[r * 16 + li];
        if (it > 0) SV4[(it - 1) * 1024 + r * 16 + li] = sv;
        if (bitr(nb0, nb1, r)) {
          float c = rsum16(sv.x * q.x + sv.y * q.y + sv.z * q.z + sv.w * q.w, hm);
          c = fabsf(c);
          const u64 cp = pk1(c);
          Acc4 we; we.lo = 0ull; we.hi = 0ull;
          afma(we, cp, *reinterpret_cast<const ulonglong2*>(&sv));
          WE4[r * 16 + li] = aunpk(we);
        }
      }
    }
    __syncthreads();

    // Phase B: warp-uniform, one task per warp, lane = 2 columns -------------
    for (int t = w; t < cnt; t += 16) {
      const int r = s.tasks[hop][t];
      unsigned mm0 = s.m0[r], mm1 = s.m1[r];
      u64 a0 = 0ull, a1 = 0ull;
      while (mm0) { const int j = __ffs(mm0) - 1;  mm0 &= mm0 - 1; a0 = add2(a0, WEq[j * 32 + l]); }
      while (mm1) { const int j = __ffs(mm1) + 31; mm1 &= mm1 - 1; a1 = add2(a1, WEq[j * 32 + l]); }
      a0 = add2(a0, a1);
      float ax, ay; upk(a0, ax, ay);
      ax = (ax >= 0.f) ? ax : 0.01f * ax;
      ay = (ay >= 0.f) ? ay : 0.01f * ay;
      const float inv = 1.f / (s.degf[r] + 1e-8f);
      ax *= inv; ay *= inv;
      const float mu  = rsum32(ax + ay) * (1.f / 64.f);
      const float dx = ax - mu, dy = ay - mu;
      const float var = rsum32(dx * dx + dy * dy) * (1.f / 64.f);
      const float rs = rsqrtf(var + 1e-5f);
      const float2 gg = gm2[l], bb = bt2[l], fv = F2[r * 32 + l];
      float2 u;
      u.x = fv.x + fmaf(gg.x * rs, dx, bb.x);
      u.y = fv.y + fmaf(gg.y * rs, dy, bb.y);
      U2[r * 32 + l] = u;
    }
    __syncthreads();

    // Phase C: relu(U @ W + b) over frontier rows ----------------------------
    if (cnt > 32) {
      for (int t2 = hw; 2 * t2 < cnt; t2 += 32) {
        const int ia = 2 * t2;
        const int ib = ia + 1;
        const int ra = s.tasks[hop][ia];
        const int rb = (ib < cnt) ? (int)s.tasks[hop][ib] : ra;   // degenerate dup OK
        const float4 bq = bi4[li];
        Acc4 aa, ab;
        aa.lo = pk2(bq.x, bq.y); aa.hi = pk2(bq.z, bq.w);
        ab = aa;
        #pragma unroll
        for (int kb = 0; kb < 16; ++kb) {
          const float4 xa = U4[ra * 16 + kb];
          const float4 xb = U4[rb * 16 + kb];
          ulonglong2 wq;
          wq = W8[(4 * kb + 0) * 16 + li]; afma(aa, pk1(xa.x), wq); afma(ab, pk1(xb.x), wq);
          wq = W8[(4 * kb + 1) * 16 + li]; afma(aa, pk1(xa.y), wq); afma(ab, pk1(xb.y), wq);
          wq = W8[(4 * kb + 2) * 16 + li]; afma(aa, pk1(xa.z), wq); afma(ab, pk1(xb.z), wq);
          wq = W8[(4 * kb + 3) * 16 + li]; afma(aa, pk1(xa.w), wq); afma(ab, pk1(xb.w), wq);
        }
        float4 fa = aunpk(aa); relu4(fa);
        float4 fb = aunpk(ab); relu4(fb);
        S4[ra * 16 + li] = fa;
        if (ib < cnt) S4[rb * 16 + li] = fb;
      }
    } else {
      int ks_sh = 0;
      if      (cnt <= 2)  ks_sh = 4;
      else if (cnt <= 4)  ks_sh = 3;
      else if (cnt <= 8)  ks_sh = 2;
      else if (cnt <= 16) ks_sh = 1;
      const int KS = 1 << ks_sh;
      const int nslots = cnt << ks_sh;
      if (hw < nslots) {
        const int t  = hw >> ks_sh;
        const int q  = hw & (KS - 1);
        const int r  = s.tasks[hop][t];
        const int nkb = 16 >> ks_sh;
        const int kb0 = q * nkb;
        Acc4 acc;
        if (ks_sh == 0) { const float4 bq = bi4[li]; acc.lo = pk2(bq.x, bq.y); acc.hi = pk2(bq.z, bq.w); }
        else            { acc.lo = 0ull; acc.hi = 0ull; }
        #pragma unroll 4
        for (int kb = kb0; kb < kb0 + nkb; ++kb) {
          const float4 xv = U4[r * 16 + kb];
          afma(acc, pk1(xv.x), W8[(4 * kb + 0) * 16 + li]);
          afma(acc, pk1(xv.y), W8[(4 * kb + 1) * 16 + li]);
          afma(acc, pk1(xv.z), W8[(4 * kb + 2) * 16 + li]);
          afma(acc, pk1(xv.w), W8[(4 * kb + 3) * 16 + li]);
        }
        float4 fa = aunpk(acc);
        if (ks_sh == 0) { relu4(fa); S4[r * 16 + li] = fa; }
        else            P4[hw * 16 + li] = fa;
      }
      __syncthreads();
      if (ks_sh > 0) {
        if (hw < cnt) {
          const int r = s.tasks[hop][hw];
          float4 acc = bi4[li];
          for (int q = 0; q < KS; ++q) add4(acc, P4[((hw << ks_sh) + q) * 16 + li]);
          relu4(acc);
          S4[r * 16 + li] = acc;
        }
      }
    }
    __syncthreads();
  }

  // ---------------- symmetric tail: each side emits its half via DSMEM ------
  CL_ARRIVE();
  CL_WAIT();
  {
    const int r = side * 32 + (tid >> 4), c4 = tid & 15;
    const int i4 = r * 16 + c4;
    // batch the three remote loads for MLP
    const float4 p0 = ld_ds4(pbase + off_SAV + (uint32_t)(0 * 1024 + i4) * 16u);
    const float4 p1 = ld_ds4(pbase + off_SAV + (uint32_t)(1 * 1024 + i4) * 16u);
    const float4 p2 = ld_ds4(pbase + off_S   + (uint32_t)i4 * 16u);
    float4 a0 = SV4[0 * 1024 + i4]; add4(a0, p0);
    float4 a1 = SV4[1 * 1024 + i4]; add4(a1, p1);
    float4 a2 = S4[i4];             add4(a2, p2);
    CL_ARRIVE();            // remote values consumed; peer may proceed
    float* ob = out + (size_t)(base + r) * 256 + c4 * 4;
    *reinterpret_cast<float4*>(ob +  64) = a0;
    *reinterpret_cast<float4*>(ob + 128) = a1;
    *reinterpret_cast<float4*>(ob + 192) = a2;
  }
  CL_WAIT();
}

} // namespace

extern "C" void kernel_launch(void* const* d_in, const int* in_sizes, int n_in,
                              void* d_out, int out_size) {
  const float* adj       = (const float*)d_in[0];
  const float* feat_node = (const float*)d_in[1];
  const int*   idx       = (const int*)  d_in[2];
  const int*   head_ids  = (const int*)  d_in[3];
  const int*   tail_ids  = (const int*)  d_in[4];
  // d_in[5] = graph_indices (implicit in block layout)
  const float* transform = (const float*)d_in[6];
  const float* embed     = (const float*)d_in[7];
  const float* w1        = (const float*)d_in[8];
  const float* b1        = (const float*)d_in[9];
  const float* w2        = (const float*)d_in[10];
  const float* b2        = (const float*)d_in[11];
  const float* gamma1    = (const float*)d_in[12];
  const float* beta1     = (const float*)d_in[13];
  const float* gamma2    = (const float*)d_in[14];
  const float* beta2     = (const float*)d_in[15];
  float* out = (float*)d_out;

  const int smem = (int)sizeof(Smem);
  cudaFuncSetAttribute(lagat_kernel, cudaFuncAttributeMaxDynamicSharedMemorySize, smem);
  lagat_kernel<<<128, NT, smem>>>(adj, feat_node, idx, head_ids, tail_ids,
                                  transform, embed, w1, b1, w2, b2,
                                  gamma1, beta1, gamma2, beta2, out);
}